// round 8
// baseline (speedup 1.0000x reference)
#include <cuda_runtime.h>
#include <cuda_bf16.h>
#include <cstdint>

typedef unsigned long long ull;

#define NR_MAX 32
#define E_MAX  2000000
#define N_MAX  200000
#define TILE_E 256            // edges per MMA tile (M=256)
#define T_MAX  (E_MAX / TILE_E + NR_MAX)

// ---------------- scratch (static device globals) ----------------------------
__device__ int g_perm[E_MAX];
__device__ int g_counts[NR_MAX];          // zero-init; scan re-zeros after use
__device__ int g_offsets[NR_MAX + 1];
__device__ int g_cursor[NR_MAX];
__device__ int g_tileBase[NR_MAX + 1];
__device__ int4 g_tinfo[T_MAX];           // (r, start, len, 0) per tile
__device__ unsigned g_done;               // k_prep completion counter
// pre-split weights [r][o][f] bf16 (8KB/rel each)
__device__ __align__(16) __nv_bfloat16 g_whi[NR_MAX * 64 * 64];
__device__ __align__(16) __nv_bfloat16 g_wlo[NR_MAX * 64 * 64];
// pre-split features: one 256B row per node = hi[64] | lo[64]
__device__ __align__(16) __nv_bfloat16 g_fsp[N_MAX * 128];

// ---------------- ptx helpers -------------------------------------------------
__device__ __forceinline__ uint32_t smem_u32(const void* p) {
    uint32_t a;
    asm("{ .reg .u64 t; cvta.to.shared.u64 t, %1; cvt.u32.u64 %0, t; }" : "=r"(a) : "l"(p));
    return a;
}
__device__ __forceinline__ void cpa16(uint32_t dst, const void* src, int sz) {
    asm volatile("cp.async.cg.shared.global [%0], [%1], 16, %2;"
                 :: "r"(dst), "l"(src), "r"(sz) : "memory");
}
__device__ __forceinline__ void cpa_commit_wait() {
    asm volatile("cp.async.commit_group;" ::: "memory");
    asm volatile("cp.async.wait_group 0;" ::: "memory");
}
__device__ __forceinline__ void ldsm4(uint32_t& r0, uint32_t& r1, uint32_t& r2, uint32_t& r3, uint32_t a) {
    asm volatile("ldmatrix.sync.aligned.m8n8.x4.shared.b16 {%0,%1,%2,%3}, [%4];"
                 : "=r"(r0), "=r"(r1), "=r"(r2), "=r"(r3) : "r"(a));
}
__device__ __forceinline__ void mma_bf16(float* d, uint32_t a0, uint32_t a1, uint32_t a2, uint32_t a3,
                                         uint32_t b0, uint32_t b1) {
    asm volatile(
        "mma.sync.aligned.m16n8k16.row.col.f32.bf16.bf16.f32 "
        "{%0,%1,%2,%3}, {%4,%5,%6,%7}, {%8,%9}, {%0,%1,%2,%3};"
        : "+f"(d[0]), "+f"(d[1]), "+f"(d[2]), "+f"(d[3])
        : "r"(a0), "r"(a1), "r"(a2), "r"(a3), "r"(b0), "r"(b1));
}
__device__ __forceinline__ void red4(float* p, float a, float b, float c, float d) {
    asm volatile("red.global.add.v4.f32 [%0], {%1,%2,%3,%4};"
                 :: "l"(p), "f"(a), "f"(b), "f"(c), "f"(d) : "memory");
}

// ---------------- K1: fused prep (+ last-block scan) ---------------------------
__global__ void k_prep(float4* out4, int n4,
                       const float* __restrict__ feat, int NF,
                       const float* __restrict__ weight, int RW,
                       const int* __restrict__ et, int E, int R) {
    int gtid = blockIdx.x * blockDim.x + threadIdx.x;
    int gsz  = gridDim.x * blockDim.x;

    for (int i = gtid; i < n4; i += gsz) out4[i] = make_float4(0.f, 0.f, 0.f, 0.f);

    for (int i = gtid; i < RW; i += gsz) {
        int r = i >> 12, f = (i >> 6) & 63, o = i & 63;
        float w = weight[i];
        __nv_bfloat16 h = __float2bfloat16(w);
        __nv_bfloat16 l = __float2bfloat16(w - __bfloat162float(h));
        g_whi[r * 4096 + o * 64 + f] = h;
        g_wlo[r * 4096 + o * 64 + f] = l;
    }

    for (int i = gtid; i < NF; i += gsz) {
        float v = feat[i];
        int n = i >> 6, f = i & 63;
        __nv_bfloat16 h = __float2bfloat16(v);
        g_fsp[n * 128 + f]      = h;
        g_fsp[n * 128 + 64 + f] = __float2bfloat16(v - __bfloat162float(h));
    }

    __shared__ int h[NR_MAX];
    if (threadIdx.x < NR_MAX) h[threadIdx.x] = 0;
    __syncthreads();
    for (int i = gtid; i < E; i += gsz) atomicAdd(&h[et[i]], 1);
    __syncthreads();
    if (threadIdx.x < NR_MAX && h[threadIdx.x]) atomicAdd(&g_counts[threadIdx.x], h[threadIdx.x]);

    // last block performs the tiny scan
    __threadfence();
    __syncthreads();
    if (threadIdx.x == 0) {
        unsigned prev = atomicAdd(&g_done, 1u);
        if (prev == gridDim.x - 1) {
            g_done = 0;
            int acc = 0, tacc = 0;
            for (int r = 0; r < R; r++) {
                g_offsets[r] = acc; g_cursor[r] = acc; g_tileBase[r] = tacc;
                int c = g_counts[r];
                g_counts[r] = 0;
                acc += c; tacc += (c + TILE_E - 1) / TILE_E;
            }
            g_offsets[R] = acc; g_tileBase[R] = tacc;
            __threadfence();
        }
    }
}

// ---------------- K3: bucket edge ids + tile-info precompute -------------------
#define SC_CH 2048
__global__ void k_scatter(const int* __restrict__ et, int E, int R) {
    __shared__ int h[NR_MAX], base[NR_MAX];
    if (threadIdx.x < NR_MAX) h[threadIdx.x] = 0;
    __syncthreads();
    int b0 = blockIdx.x * SC_CH;
    int myr[8], myrank[8];
#pragma unroll
    for (int j = 0; j < 8; j++) {
        int i = b0 + j * 256 + threadIdx.x;
        myr[j] = -1;
        if (i < E) { myr[j] = et[i]; myrank[j] = atomicAdd(&h[myr[j]], 1); }
    }
    __syncthreads();
    if (threadIdx.x < R && h[threadIdx.x] > 0)
        base[threadIdx.x] = atomicAdd(&g_cursor[threadIdx.x], h[threadIdx.x]);
    __syncthreads();
#pragma unroll
    for (int j = 0; j < 8; j++) {
        int i = b0 + j * 256 + threadIdx.x;
        if (i < E) g_perm[base[myr[j]] + myrank[j]] = i;
    }

    // piggyback: per-tile info
    int t = blockIdx.x * blockDim.x + threadIdx.x;
    int T = g_tileBase[R];
    if (t < T) {
        int r = 0;
#pragma unroll 1
        for (int i = 1; i < NR_MAX; i++)
            if (i < R && t >= g_tileBase[i]) r = i;
        int start = g_offsets[r] + (t - g_tileBase[r]) * TILE_E;
        int len = min(TILE_E, g_offsets[r + 1] - start);
        g_tinfo[t] = make_int4(r, start, len, 0);
    }
}

// ---------------- K4: HMMA grouped-GEMM tile (M=256, 512 thr, m32n32/warp) -----
// 128B pitch; 16B-chunk index XOR (row & 7) swizzle.
#define OFF_DST  0                          // int[256]
#define OFF_A    1024
#define A_HALF   (256 * 128)                // 32768
#define OFF_B    (OFF_A + 2 * A_HALF)       // 66560
#define B_HALF   (64 * 128)                 // 8192
#define SMEM_SZ  (OFF_B + 2 * B_HALF)       // 82944

__global__ __launch_bounds__(512, 2) void k_main(
    const int* __restrict__ src, const int* __restrict__ dst,
    float* __restrict__ out, int R)
{
    extern __shared__ char smem[];
    uint32_t sb = smem_u32(smem);
    int tid = threadIdx.x;
    int wid = tid >> 5, lid = tid & 31;

    int t = blockIdx.x;
    if (t >= g_tileBase[R]) return;
    int4 ti = g_tinfo[t];                   // r, start, len
    int r = ti.x, start = ti.y, len = ti.z;

    int* dsts = (int*)(smem + OFF_DST);

    // Phase A: gather (2 threads per edge: half=0 -> hi 128B, half=1 -> lo 128B)
    {
        int e2 = tid >> 1, half = tid & 1;
        int s = -1;
        if (e2 < len) {
            int idx = g_perm[start + e2];
            s = src[idx];
            if (half == 0) dsts[e2] = dst[idx];
        }
        const char* fs = (const char*)g_fsp + (size_t)(s >= 0 ? s : 0) * 256 + half * 128;
        int sz = (s >= 0) ? 16 : 0;
        uint32_t da = sb + OFF_A + half * A_HALF + e2 * 128;
        int r7 = e2 & 7;
#pragma unroll
        for (int c = 0; c < 8; c++) cpa16(da + ((c ^ r7) << 4), fs + c * 16, sz);
    }
    // B tiles: 512 hi + 512 lo 16B chunks (swizzled), 1 hi + 1 lo per thread
    {
        const char* wh = (const char*)g_whi + (size_t)r * 8192;
        const char* wl = (const char*)g_wlo + (size_t)r * 8192;
        int c = tid;                          // 0..511
        int row = c >> 3, col = c & 7;
        uint32_t doff = row * 128 + (((col ^ (row & 7))) << 4);
        cpa16(sb + OFF_B + doff, wh + row * 128 + col * 16, 16);
        cpa16(sb + OFF_B + B_HALF + doff, wl + row * 128 + col * 16, 16);
    }
    cpa_commit_wait();
    __syncthreads();

    // MMA: D = aH*bH + aH*bL + aL*bH
    // 16 warps: rowg = wid>>1 (8 groups x 32 rows), colg = wid&1 (2 groups x 32 cols)
    int rowg = wid >> 1, colg = wid & 1;
    float acc[2][4][4];
#pragma unroll
    for (int a = 0; a < 2; a++)
#pragma unroll
        for (int b = 0; b < 4; b++)
#pragma unroll
            for (int c = 0; c < 4; c++) acc[a][b][c] = 0.f;

    int rA0 = rowg * 32 + (lid & 15);
    int rA7 = rA0 & 7;                       // same for both row tiles (offset 16)
    int cA0 = lid >> 4;
    int rowBb = colg * 32 + (lid & 7) + ((lid >> 4) << 3);
    int cB0 = (lid >> 3) & 1;

#pragma unroll
    for (int kk = 0; kk < 4; kk++) {
        uint32_t aoff = (uint32_t)(((cA0 + 2 * kk) ^ rA7) << 4);
        uint32_t aH[2][4], aL[2][4];
#pragma unroll
        for (int rt = 0; rt < 2; rt++) {
            uint32_t aAddr = sb + OFF_A + (uint32_t)(rA0 + rt * 16) * 128 + aoff;
            ldsm4(aH[rt][0], aH[rt][1], aH[rt][2], aH[rt][3], aAddr);
            ldsm4(aL[rt][0], aL[rt][1], aL[rt][2], aL[rt][3], aAddr + A_HALF);
        }
#pragma unroll
        for (int p = 0; p < 2; p++) {
            int rowB = rowBb + p * 16;
            uint32_t bAddr = sb + OFF_B + (uint32_t)rowB * 128
                           + (uint32_t)(((cB0 + 2 * kk) ^ (rowB & 7)) << 4);
            uint32_t bh0, bh1, bh2, bh3, bl0, bl1, bl2, bl3;
            ldsm4(bh0, bh1, bh2, bh3, bAddr);
            ldsm4(bl0, bl1, bl2, bl3, bAddr + B_HALF);
#pragma unroll
            for (int rt = 0; rt < 2; rt++) {
                mma_bf16(acc[rt][2 * p],     aH[rt][0], aH[rt][1], aH[rt][2], aH[rt][3], bh0, bh1);
                mma_bf16(acc[rt][2 * p],     aH[rt][0], aH[rt][1], aH[rt][2], aH[rt][3], bl0, bl1);
                mma_bf16(acc[rt][2 * p],     aL[rt][0], aL[rt][1], aL[rt][2], aL[rt][3], bh0, bh1);
                mma_bf16(acc[rt][2 * p + 1], aH[rt][0], aH[rt][1], aH[rt][2], aH[rt][3], bh2, bh3);
                mma_bf16(acc[rt][2 * p + 1], aH[rt][0], aH[rt][1], aH[rt][2], aH[rt][3], bl2, bl3);
                mma_bf16(acc[rt][2 * p + 1], aL[rt][0], aL[rt][1], aL[rt][2], aL[rt][3], bh2, bh3);
            }
        }
    }

    // Epilogue: shfl-pair repack + red.global.add.v4
    int g = lid >> 2, tig = lid & 3;
    bool even = (tig & 1) == 0;
    int cb = colg * 32 + (even ? (tig * 2) : ((tig - 1) * 2));
#pragma unroll
    for (int rt = 0; rt < 2; rt++) {
        int row = rowg * 32 + rt * 16 + g + (even ? 0 : 8);
        bool live = row < len;
        float* pbase = live ? (out + (size_t)dsts[row] * 64 + cb) : out;
#pragma unroll
        for (int nt = 0; nt < 4; nt++) {
            float o0 = __shfl_xor_sync(0xffffffffu, acc[rt][nt][0], 1);
            float o1 = __shfl_xor_sync(0xffffffffu, acc[rt][nt][1], 1);
            float o2 = __shfl_xor_sync(0xffffffffu, acc[rt][nt][2], 1);
            float o3 = __shfl_xor_sync(0xffffffffu, acc[rt][nt][3], 1);
            if (live) {
                if (even) red4(pbase + nt * 8, acc[rt][nt][0], acc[rt][nt][1], o0, o1);
                else      red4(pbase + nt * 8, o2, o3, acc[rt][nt][2], acc[rt][nt][3]);
            }
        }
    }
}

// ---------------- launch ------------------------------------------------------
extern "C" void kernel_launch(void* const* d_in, const int* in_sizes, int n_in,
                              void* d_out, int out_size) {
    const float* feat   = (const float*)d_in[0];
    const float* weight = (const float*)d_in[1];
    const int*   src    = (const int*)d_in[2];
    const int*   dst    = (const int*)d_in[3];
    const int*   et     = (const int*)d_in[4];
    float*       out    = (float*)d_out;

    int NF = in_sizes[0];
    int RW = in_sizes[1];
    int E  = in_sizes[2];
    int R  = RW / 4096;
    if (R < 1) R = 1;
    if (R > NR_MAX) R = NR_MAX;

    cudaFuncSetAttribute(k_main, cudaFuncAttributeMaxDynamicSharedMemorySize, SMEM_SZ);

    int n4 = out_size / 4;
    k_prep<<<1184, 256>>>((float4*)d_out, n4, feat, NF, weight, RW, et, E, R);
    k_scatter<<<(E + SC_CH - 1) / SC_CH, 256>>>(et, E, R);

    int maxTiles = (E + TILE_E - 1) / TILE_E + R;
    k_main<<<maxTiles, 512, SMEM_SZ>>>(src, dst, out, R);
}

// round 10
// speedup vs baseline: 1.0911x; 1.0911x over previous
#include <cuda_runtime.h>
#include <cuda_bf16.h>
#include <cstdint>

typedef unsigned long long ull;

#define NR_MAX 32
#define E_MAX  2000000
#define N_MAX  200000
#define TILE_E 128            // edges per MMA tile (M=128)
#define T_MAX  (E_MAX / TILE_E + NR_MAX)

// ---------------- scratch (static device globals) ----------------------------
__device__ int g_perm[E_MAX];
__device__ int g_counts[NR_MAX];          // zero-init; scan re-zeros after use
__device__ int g_offsets[NR_MAX + 1];
__device__ int g_cursor[NR_MAX];
__device__ int g_tileBase[NR_MAX + 1];
__device__ int4 g_tinfo[T_MAX];           // (r, start, len, 0) per tile
__device__ unsigned g_done;               // k_prep completion counter
// pre-split weights [r][o][f] bf16 (8KB/rel each)
__device__ __align__(16) __nv_bfloat16 g_whi[NR_MAX * 64 * 64];
__device__ __align__(16) __nv_bfloat16 g_wlo[NR_MAX * 64 * 64];
// pre-split features: one 256B row per node = hi[64] | lo[64]
__device__ __align__(16) __nv_bfloat16 g_fsp[N_MAX * 128];

// ---------------- ptx helpers -------------------------------------------------
__device__ __forceinline__ uint32_t smem_u32(const void* p) {
    uint32_t a;
    asm("{ .reg .u64 t; cvta.to.shared.u64 t, %1; cvt.u32.u64 %0, t; }" : "=r"(a) : "l"(p));
    return a;
}
__device__ __forceinline__ void cpa16(uint32_t dst, const void* src, int sz) {
    asm volatile("cp.async.cg.shared.global [%0], [%1], 16, %2;"
                 :: "r"(dst), "l"(src), "r"(sz) : "memory");
}
__device__ __forceinline__ void cpa_commit() {
    asm volatile("cp.async.commit_group;" ::: "memory");
}
__device__ __forceinline__ void cpa_wait1() {
    asm volatile("cp.async.wait_group 1;" ::: "memory");
}
__device__ __forceinline__ void cpa_wait0() {
    asm volatile("cp.async.wait_group 0;" ::: "memory");
}
__device__ __forceinline__ void ldsm4(uint32_t& r0, uint32_t& r1, uint32_t& r2, uint32_t& r3, uint32_t a) {
    asm volatile("ldmatrix.sync.aligned.m8n8.x4.shared.b16 {%0,%1,%2,%3}, [%4];"
                 : "=r"(r0), "=r"(r1), "=r"(r2), "=r"(r3) : "r"(a));
}
__device__ __forceinline__ void mma_bf16(float* d, uint32_t a0, uint32_t a1, uint32_t a2, uint32_t a3,
                                         uint32_t b0, uint32_t b1) {
    asm volatile(
        "mma.sync.aligned.m16n8k16.row.col.f32.bf16.bf16.f32 "
        "{%0,%1,%2,%3}, {%4,%5,%6,%7}, {%8,%9}, {%0,%1,%2,%3};"
        : "+f"(d[0]), "+f"(d[1]), "+f"(d[2]), "+f"(d[3])
        : "r"(a0), "r"(a1), "r"(a2), "r"(a3), "r"(b0), "r"(b1));
}
__device__ __forceinline__ void red2(float* p, float a, float b) {
    asm volatile("red.global.add.v2.f32 [%0], {%1,%2};"
                 :: "l"(p), "f"(a), "f"(b) : "memory");
}

// ---------------- K1: fused prep (+ last-block scan) ---------------------------
__global__ void k_prep(float4* out4, int n4,
                       const float* __restrict__ feat, int NF,
                       const float* __restrict__ weight, int RW,
                       const int* __restrict__ et, int E, int R) {
    int gtid = blockIdx.x * blockDim.x + threadIdx.x;
    int gsz  = gridDim.x * blockDim.x;

    for (int i = gtid; i < n4; i += gsz) out4[i] = make_float4(0.f, 0.f, 0.f, 0.f);

    for (int i = gtid; i < RW; i += gsz) {
        int r = i >> 12, f = (i >> 6) & 63, o = i & 63;
        float w = weight[i];
        __nv_bfloat16 h = __float2bfloat16(w);
        __nv_bfloat16 l = __float2bfloat16(w - __bfloat162float(h));
        g_whi[r * 4096 + o * 64 + f] = h;
        g_wlo[r * 4096 + o * 64 + f] = l;
    }

    for (int i = gtid; i < NF; i += gsz) {
        float v = feat[i];
        int n = i >> 6, f = i & 63;
        __nv_bfloat16 h = __float2bfloat16(v);
        g_fsp[n * 128 + f]      = h;
        g_fsp[n * 128 + 64 + f] = __float2bfloat16(v - __bfloat162float(h));
    }

    __shared__ int h[NR_MAX];
    if (threadIdx.x < NR_MAX) h[threadIdx.x] = 0;
    __syncthreads();
    for (int i = gtid; i < E; i += gsz) atomicAdd(&h[et[i]], 1);
    __syncthreads();
    if (threadIdx.x < NR_MAX && h[threadIdx.x]) atomicAdd(&g_counts[threadIdx.x], h[threadIdx.x]);

    // last block performs the tiny scan
    __threadfence();
    __syncthreads();
    if (threadIdx.x == 0) {
        unsigned prev = atomicAdd(&g_done, 1u);
        if (prev == gridDim.x - 1) {
            g_done = 0;
            int acc = 0, tacc = 0;
            for (int r = 0; r < R; r++) {
                g_offsets[r] = acc; g_cursor[r] = acc; g_tileBase[r] = tacc;
                int c = g_counts[r];
                g_counts[r] = 0;
                acc += c; tacc += (c + TILE_E - 1) / TILE_E;
            }
            g_offsets[R] = acc; g_tileBase[R] = tacc;
            __threadfence();
        }
    }
}

// ---------------- K3: bucket edge ids + tile-info precompute -------------------
#define SC_CH 2048
__global__ void k_scatter(const int* __restrict__ et, int E, int R) {
    __shared__ int h[NR_MAX], base[NR_MAX];
    if (threadIdx.x < NR_MAX) h[threadIdx.x] = 0;
    __syncthreads();
    int b0 = blockIdx.x * SC_CH;
    int myr[8], myrank[8];
#pragma unroll
    for (int j = 0; j < 8; j++) {
        int i = b0 + j * 256 + threadIdx.x;
        myr[j] = -1;
        if (i < E) { myr[j] = et[i]; myrank[j] = atomicAdd(&h[myr[j]], 1); }
    }
    __syncthreads();
    if (threadIdx.x < R && h[threadIdx.x] > 0)
        base[threadIdx.x] = atomicAdd(&g_cursor[threadIdx.x], h[threadIdx.x]);
    __syncthreads();
#pragma unroll
    for (int j = 0; j < 8; j++) {
        int i = b0 + j * 256 + threadIdx.x;
        if (i < E) g_perm[base[myr[j]] + myrank[j]] = i;
    }

    // piggyback: per-tile info
    int t = blockIdx.x * blockDim.x + threadIdx.x;
    int T = g_tileBase[R];
    if (t < T) {
        int r = 0;
#pragma unroll 1
        for (int i = 1; i < NR_MAX; i++)
            if (i < R && t >= g_tileBase[i]) r = i;
        int start = g_offsets[r] + (t - g_tileBase[r]) * TILE_E;
        int len = min(TILE_E, g_offsets[r + 1] - start);
        g_tinfo[t] = make_int4(r, start, len, 0);
    }
}

// ---------------- K4: HMMA grouped-GEMM tile (m32n32 warps, split-commit) ------
// 128B pitch; 16B-chunk index XOR (row & 7) swizzle.
#define OFF_DST  0                          // int[128]
#define OFF_A    1024
#define A_HALF   (128 * 128)                // 16384
#define OFF_B    (OFF_A + 2 * A_HALF)       // 33792
#define B_HALF   (64 * 128)                 // 8192
#define SMEM_SZ  (OFF_B + 2 * B_HALF)       // 50176

__global__ __launch_bounds__(256, 4) void k_main(
    const int* __restrict__ src, const int* __restrict__ dst,
    float* __restrict__ out, int R)
{
    extern __shared__ char smem[];
    uint32_t sb = smem_u32(smem);
    int tid = threadIdx.x;
    int wid = tid >> 5, lid = tid & 31;

    int t = blockIdx.x;
    if (t >= g_tileBase[R]) return;
    int4 ti = g_tinfo[t];                   // r, start, len
    int r = ti.x, start = ti.y, len = ti.z;

    int* dsts = (int*)(smem + OFF_DST);

    // Phase A: gather. Group 0 = A cols 0..31 (chunks 0..3) + full B.
    //          Group 1 = A cols 32..63 (chunks 4..7).
    int e2 = tid >> 1, half = tid & 1;
    {
        int s = -1;
        if (e2 < len) {
            int idx = g_perm[start + e2];
            s = src[idx];
            if (half == 0) dsts[e2] = dst[idx];
        }
        const char* fs = (const char*)g_fsp + (size_t)(s >= 0 ? s : 0) * 256 + half * 128;
        int sz = (s >= 0) ? 16 : 0;
        uint32_t da = sb + OFF_A + half * A_HALF + e2 * 128;
        int r7 = e2 & 7;
#pragma unroll
        for (int c = 0; c < 4; c++) cpa16(da + ((c ^ r7) << 4), fs + c * 16, sz);
        // B tiles: 512 hi + 512 lo 16B chunks (swizzled), 2+2 per thread
        {
            const char* wh = (const char*)g_whi + (size_t)r * 8192;
            const char* wl = (const char*)g_wlo + (size_t)r * 8192;
#pragma unroll
            for (int j = 0; j < 2; j++) {
                int c = j * 256 + tid;            // 0..511
                int row = c >> 3, col = c & 7;
                uint32_t doff = row * 128 + (((col ^ (row & 7))) << 4);
                cpa16(sb + OFF_B + doff, wh + row * 128 + col * 16, 16);
                cpa16(sb + OFF_B + B_HALF + doff, wl + row * 128 + col * 16, 16);
            }
        }
        cpa_commit();                          // group 0
#pragma unroll
        for (int c = 4; c < 8; c++) cpa16(da + ((c ^ r7) << 4), fs + c * 16, sz);
        cpa_commit();                          // group 1
    }

    // m32n32 warp layout: rowg = wid>>1 (4 groups), colg = wid&1 (2 groups)
    int rowg = wid >> 1, colg = wid & 1;
    float acc[2][4][4];
#pragma unroll
    for (int a = 0; a < 2; a++)
#pragma unroll
        for (int b = 0; b < 4; b++)
#pragma unroll
            for (int c = 0; c < 4; c++) acc[a][b][c] = 0.f;

    int rA0 = rowg * 32 + (lid & 15);
    int rA7 = rA0 & 7;                        // same parity for rt offset 16
    int cA0 = lid >> 4;
    int rowBb = colg * 32 + (lid & 7) + ((lid >> 4) << 3);
    int cB0 = (lid >> 3) & 1;

    cpa_wait1();                              // group 0 (A cols 0..31 + B) done
    __syncthreads();

#pragma unroll
    for (int kh = 0; kh < 2; kh++) {          // k halves
        if (kh == 1) {                        // wait for A cols 32..63
            cpa_wait0();
            __syncthreads();
        }
#pragma unroll
        for (int ki = 0; ki < 2; ki++) {
            int kk = kh * 2 + ki;
            // hoist B fragments for this kk (both p, hi+lo)
            uint32_t bh[2][4], bl[2][4];
#pragma unroll
            for (int p = 0; p < 2; p++) {
                int rowB = rowBb + p * 16;
                uint32_t bAddr = sb + OFF_B + (uint32_t)rowB * 128
                               + (uint32_t)(((cB0 + 2 * kk) ^ (rowB & 7)) << 4);
                ldsm4(bh[p][0], bh[p][1], bh[p][2], bh[p][3], bAddr);
                ldsm4(bl[p][0], bl[p][1], bl[p][2], bl[p][3], bAddr + B_HALF);
            }
            uint32_t aoff = (uint32_t)(((cA0 + 2 * kk) ^ rA7) << 4);
#pragma unroll
            for (int rt = 0; rt < 2; rt++) {
                uint32_t aAddr = sb + OFF_A + (uint32_t)(rA0 + rt * 16) * 128 + aoff;
                uint32_t aH0, aH1, aH2, aH3, aL0, aL1, aL2, aL3;
                ldsm4(aH0, aH1, aH2, aH3, aAddr);
                ldsm4(aL0, aL1, aL2, aL3, aAddr + A_HALF);
#pragma unroll
                for (int p = 0; p < 2; p++) {
                    mma_bf16(acc[rt][2 * p],     aH0, aH1, aH2, aH3, bh[p][0], bh[p][1]);
                    mma_bf16(acc[rt][2 * p],     aH0, aH1, aH2, aH3, bl[p][0], bl[p][1]);
                    mma_bf16(acc[rt][2 * p],     aL0, aL1, aL2, aL3, bh[p][0], bh[p][1]);
                    mma_bf16(acc[rt][2 * p + 1], aH0, aH1, aH2, aH3, bh[p][2], bh[p][3]);
                    mma_bf16(acc[rt][2 * p + 1], aH0, aH1, aH2, aH3, bl[p][2], bl[p][3]);
                    mma_bf16(acc[rt][2 * p + 1], aL0, aL1, aL2, aL3, bh[p][2], bh[p][3]);
                }
            }
        }
    }

    // Epilogue: direct v2 reductions from fragment layout (no shfl)
    int g = lid >> 2, tig = lid & 3;
    int colb = colg * 32 + tig * 2;
#pragma unroll
    for (int rt = 0; rt < 2; rt++) {
        int row0 = rowg * 32 + rt * 16 + g;
        int row1 = row0 + 8;
        bool l0 = row0 < len, l1 = row1 < len;
        float* p0 = l0 ? (out + (size_t)dsts[row0] * 64 + colb) : out;
        float* p1 = l1 ? (out + (size_t)dsts[row1] * 64 + colb) : out;
#pragma unroll
        for (int nt = 0; nt < 4; nt++) {
            if (l0) red2(p0 + nt * 8, acc[rt][nt][0], acc[rt][nt][1]);
            if (l1) red2(p1 + nt * 8, acc[rt][nt][2], acc[rt][nt][3]);
        }
    }
}

// ---------------- launch ------------------------------------------------------
extern "C" void kernel_launch(void* const* d_in, const int* in_sizes, int n_in,
                              void* d_out, int out_size) {
    const float* feat   = (const float*)d_in[0];
    const float* weight = (const float*)d_in[1];
    const int*   src    = (const int*)d_in[2];
    const int*   dst    = (const int*)d_in[3];
    const int*   et     = (const int*)d_in[4];
    float*       out    = (float*)d_out;

    int NF = in_sizes[0];
    int RW = in_sizes[1];
    int E  = in_sizes[2];
    int R  = RW / 4096;
    if (R < 1) R = 1;
    if (R > NR_MAX) R = NR_MAX;

    cudaFuncSetAttribute(k_main, cudaFuncAttributeMaxDynamicSharedMemorySize, SMEM_SZ);

    int n4 = out_size / 4;
    k_prep<<<1184, 256>>>((float4*)d_out, n4, feat, NF, weight, RW, et, E, R);
    k_scatter<<<(E + SC_CH - 1) / SC_CH, 256>>>(et, E, R);

    int maxTiles = (E + TILE_E - 1) / TILE_E + R;
    k_main<<<maxTiles, 256, SMEM_SZ>>>(src, dst, out, R);
}